// round 1
// baseline (speedup 1.0000x reference)
#include <cuda_runtime.h>

#define N 8192
#define D 256
#define BM 128
#define BN 128
#define BK 32
#define NSUB 8       // 128-col subtiles per block chunk (1024 cols)
#define CCHUNKS 8    // grid.y col chunks

// Scratch (device globals: allowed; no allocation)
__device__ float g_sq[N];
__device__ unsigned long long g_pkey[CCHUNKS * N];

// ---------------------------------------------------------------------------
// Row squared-norms: one warp per row
// ---------------------------------------------------------------------------
__global__ void norms_kernel(const float* __restrict__ A) {
    int row  = blockIdx.x * 8 + (threadIdx.x >> 5);
    int lane = threadIdx.x & 31;
    const float4* a = (const float4*)(A + (size_t)row * D);
    float s = 0.f;
#pragma unroll
    for (int q = 0; q < 2; ++q) {
        float4 v = a[lane + 32 * q];
        s += v.x * v.x + v.y * v.y + v.z * v.z + v.w * v.w;
    }
#pragma unroll
    for (int o = 16; o; o >>= 1) s += __shfl_xor_sync(0xffffffffu, s, o);
    if (lane == 0) g_sq[row] = s;
}

// ---------------------------------------------------------------------------
// Fused Gram-tile + masked argmin.
// Block: 256 threads = 16x16. Each thread: 8x8 micro-tile (strided by 16).
// gridDim = (64 row tiles, 8 col chunks). Each block scans 1024 columns.
// ---------------------------------------------------------------------------
__global__ __launch_bounds__(256) void argmin_kernel(const float* __restrict__ A,
                                                     const int* __restrict__ host) {
    __shared__ __align__(16) float As[BK][BM + 1];  // [k][row], pad->129
    __shared__ __align__(16) float Bs[BK][BN + 1];

    const int tid = threadIdx.x;
    const int tx  = tid & 15;   // col group
    const int ty  = tid >> 4;   // row group
    const int row_base = blockIdx.x * BM;
    const int chunk    = blockIdx.y;

    // Per-thread row metadata (rows row_base + ty + 16*i)
    int   hr[8];
    float sr[8];
#pragma unroll
    for (int i = 0; i < 8; ++i) {
        int r = row_base + ty + 16 * i;
        hr[i] = host[r];
        sr[i] = g_sq[r];
    }

    unsigned long long best[8];
#pragma unroll
    for (int i = 0; i < 8; ++i) best[i] = 0xFFFFFFFFFFFFFFFFull;

    for (int sub = 0; sub < NSUB; ++sub) {
        const int col_base = chunk * (NSUB * BN) + sub * BN;

        float acc[8][8];
#pragma unroll
        for (int i = 0; i < 8; ++i)
#pragma unroll
            for (int j = 0; j < 8; ++j) acc[i][j] = 0.f;

        for (int ks = 0; ks < D / BK; ++ks) {
            const int kb = ks * BK;
            // Cooperative loads: 1024 float4 per tile, 4 per thread.
#pragma unroll
            for (int p = 0; p < 4; ++p) {
                int f   = p * 256 + tid;
                int row = f >> 3;
                int k4  = f & 7;
                float4 va = *(const float4*)(A + (size_t)(row_base + row) * D + kb + k4 * 4);
                As[k4 * 4 + 0][row] = va.x;
                As[k4 * 4 + 1][row] = va.y;
                As[k4 * 4 + 2][row] = va.z;
                As[k4 * 4 + 3][row] = va.w;
                float4 vb = *(const float4*)(A + (size_t)(col_base + row) * D + kb + k4 * 4);
                Bs[k4 * 4 + 0][row] = vb.x;
                Bs[k4 * 4 + 1][row] = vb.y;
                Bs[k4 * 4 + 2][row] = vb.z;
                Bs[k4 * 4 + 3][row] = vb.w;
            }
            __syncthreads();

#pragma unroll
            for (int kk = 0; kk < BK; ++kk) {
                float a[8], b[8];
#pragma unroll
                for (int i = 0; i < 8; ++i) a[i] = As[kk][ty + 16 * i];
#pragma unroll
                for (int j = 0; j < 8; ++j) b[j] = Bs[kk][tx + 16 * j];
#pragma unroll
                for (int i = 0; i < 8; ++i)
#pragma unroll
                    for (int j = 0; j < 8; ++j)
                        acc[i][j] = fmaf(a[i], b[j], acc[i][j]);
            }
            __syncthreads();
        }

        // Epilogue: d2 = sq_r + sq_c - 2*dot, mask same-host (covers diagonal),
        // pack (d2_bits, col) -> running min (ties -> smaller index, like argmin).
#pragma unroll
        for (int j = 0; j < 8; ++j) {
            int   c  = col_base + tx + 16 * j;
            int   hc = host[c];
            float sc = g_sq[c];
#pragma unroll
            for (int i = 0; i < 8; ++i) {
                float d2 = fmaxf(sr[i] + sc - 2.0f * acc[i][j], 0.0f);
                if (hc != hr[i]) {
                    unsigned long long key =
                        ((unsigned long long)__float_as_uint(d2) << 32) | (unsigned int)c;
                    if (key < best[i]) best[i] = key;
                }
            }
        }
    }

    // Cross-tx reduction via smem (reuse As: 16*128*8 = 16 KB <= sizeof(As))
    __syncthreads();
    unsigned long long* red = (unsigned long long*)&As[0][0];
#pragma unroll
    for (int i = 0; i < 8; ++i) red[tx * 128 + (ty + 16 * i)] = best[i];
    __syncthreads();

    if (tid < 128) {
        unsigned long long m = red[tid];
#pragma unroll
        for (int t = 1; t < 16; ++t) {
            unsigned long long v = red[t * 128 + tid];
            if (v < m) m = v;
        }
        g_pkey[chunk * N + row_base + tid] = m;
    }
}

// ---------------------------------------------------------------------------
// Finalize: per-row min over 8 chunk partials, then gather e_actv[idx] -> out.
// One block (64 threads) per row; each thread copies one float4.
// ---------------------------------------------------------------------------
__global__ void finalize_kernel(const float* __restrict__ A, float* __restrict__ out_an) {
    const int row = blockIdx.x;
    unsigned long long m = 0xFFFFFFFFFFFFFFFFull;
#pragma unroll
    for (int p = 0; p < CCHUNKS; ++p) {
        unsigned long long v = g_pkey[p * N + row];
        if (v < m) m = v;
    }
    const int idx = (int)(m & 0xFFFFFFFFu);
    const float4* src = (const float4*)(A + (size_t)idx * D);
    float4* dst = (float4*)(out_an + (size_t)row * D);
    dst[threadIdx.x] = src[threadIdx.x];
}

// ---------------------------------------------------------------------------
extern "C" void kernel_launch(void* const* d_in, const int* in_sizes, int n_in,
                              void* d_out, int out_size) {
    const float* e_actv = (const float*)d_in[0];
    const float* e_ap   = (const float*)d_in[1];
    const int*   host   = (const int*)d_in[2];
    float* out = (float*)d_out;
    const size_t nd = (size_t)N * D;

    // Output tuple layout: [e_actv | e_ap | e_an]
    cudaMemcpyAsync(out,      e_actv, nd * sizeof(float), cudaMemcpyDeviceToDevice, 0);
    cudaMemcpyAsync(out + nd, e_ap,   nd * sizeof(float), cudaMemcpyDeviceToDevice, 0);

    norms_kernel<<<N / 8, 256>>>(e_actv);
    argmin_kernel<<<dim3(N / BM, CCHUNKS), 256>>>(e_actv, host);
    finalize_kernel<<<N, 64>>>(e_actv, out + 2 * nd);
}

// round 4
// speedup vs baseline: 3.2942x; 3.2942x over previous
#include <cuda_runtime.h>
#include <cuda_bf16.h>
#include <cstdint>

#define N 8192
#define D 256
#define BM 128
#define BN 128
#define CCHUNKS 16
#define NSUB 4          // 128-col subtiles per CTA (16 chunks * 4 * 128 = 8192)

// ---- smem layout (bytes) ----
#define SM_A     0                    // A: 16 chunks (8 hi + 8 lo) * 8KB = 128KB
#define SM_B     (SM_A + 131072)      // B: 2 stages * (hi+lo) * 8KB = 32KB
#define SM_HC    (SM_B + 32768)       // 128 ints
#define SM_SC    (SM_HC + 512)        // 128 floats
#define SM_RED   (SM_SC + 512)        // 128 * 2 u64
#define SM_TOTAL (SM_RED + 2048)      // 166912 bytes

// ---- device scratch (no allocation) ----
__device__ float g_sq[N];
__device__ __align__(16) uint32_t g_hi[N * (D / 2)];   // bf16x2 packed
__device__ __align__(16) uint32_t g_lo[N * (D / 2)];
__device__ unsigned long long g_pkey[CCHUNKS * N];

// ============================ PTX helpers ============================
__device__ __forceinline__ uint32_t smem_to_u32(const void* p) {
    uint32_t a;
    asm("{ .reg .u64 t; cvta.to.shared.u64 t, %1; cvt.u32.u64 %0, t; }" : "=r"(a) : "l"(p));
    return a;
}
#define CP_ASYNC16(dst, src) \
    asm volatile("cp.async.cg.shared.global [%0], [%1], 16;" :: "r"(dst), "l"(src))
#define CP_COMMIT() asm volatile("cp.async.commit_group;" ::: "memory")
#define CP_WAIT0()  asm volatile("cp.async.wait_group 0;" ::: "memory")

#define LDSM_X4(r, addr) \
    asm volatile("ldmatrix.sync.aligned.m8n8.x4.shared.b16 {%0,%1,%2,%3}, [%4];" \
        : "=r"((r)[0]), "=r"((r)[1]), "=r"((r)[2]), "=r"((r)[3]) : "r"(addr))

#define MMA16816(c, a, b0, b1) \
    asm volatile("mma.sync.aligned.m16n8k16.row.col.f32.bf16.bf16.f32 " \
        "{%0,%1,%2,%3}, {%4,%5,%6,%7}, {%8,%9}, {%0,%1,%2,%3};" \
        : "+f"((c)[0]), "+f"((c)[1]), "+f"((c)[2]), "+f"((c)[3]) \
        : "r"((a)[0]), "r"((a)[1]), "r"((a)[2]), "r"((a)[3]), "r"(b0), "r"(b1))

// 64B-row chunk swizzle: 8 consecutive rows hit 8 distinct 16B bank-groups.
__device__ __forceinline__ uint32_t swz(int r, int c16) {
    return (uint32_t)(r * 64 + ((c16 ^ ((r >> 1) & 3)) << 4));
}

__device__ __forceinline__ unsigned long long shfl_xor_u64(unsigned long long v, int m) {
    uint32_t lo = (uint32_t)v, hi = (uint32_t)(v >> 32);
    lo = __shfl_xor_sync(0xffffffffu, lo, m);
    hi = __shfl_xor_sync(0xffffffffu, hi, m);
    return ((unsigned long long)hi << 32) | lo;
}
__device__ __forceinline__ unsigned long long umin64(unsigned long long a, unsigned long long b) {
    return a < b ? a : b;
}

// ============================================================================
// Split A -> bf16 hi/lo + row norms. One warp per row.
// ============================================================================
__global__ void split_norms_kernel(const float* __restrict__ A) {
    int row  = blockIdx.x * 8 + (threadIdx.x >> 5);
    int lane = threadIdx.x & 31;
    const float4* a = (const float4*)(A + (size_t)row * D);
    float s = 0.f;
#pragma unroll
    for (int q = 0; q < 2; ++q) {
        float4 v = a[lane + 32 * q];
        s += v.x * v.x + v.y * v.y + v.z * v.z + v.w * v.w;
        __nv_bfloat162 h0 = __floats2bfloat162_rn(v.x, v.y);
        __nv_bfloat162 h1 = __floats2bfloat162_rn(v.z, v.w);
        float lx = v.x - __bfloat162float(h0.x);
        float ly = v.y - __bfloat162float(h0.y);
        float lz = v.z - __bfloat162float(h1.x);
        float lw = v.w - __bfloat162float(h1.y);
        __nv_bfloat162 l0 = __floats2bfloat162_rn(lx, ly);
        __nv_bfloat162 l1 = __floats2bfloat162_rn(lz, lw);
        uint2 hv = make_uint2(*reinterpret_cast<uint32_t*>(&h0), *reinterpret_cast<uint32_t*>(&h1));
        uint2 lv = make_uint2(*reinterpret_cast<uint32_t*>(&l0), *reinterpret_cast<uint32_t*>(&l1));
        size_t w = (size_t)row * (D / 2) + (lane + 32 * q) * 2;
        *(uint2*)(g_hi + w) = hv;
        *(uint2*)(g_lo + w) = lv;
    }
#pragma unroll
    for (int o = 16; o; o >>= 1) s += __shfl_xor_sync(0xffffffffu, s, o);
    if (lane == 0) g_sq[row] = s;
}

// ============================================================================
// bf16x3 Gram tiles via mma.sync.m16n8k16 + fused masked argmin.
// Block 256 threads = 8 warps (warp_m 0..3, warp_n 0..1); warp tile 32x64.
// ============================================================================
__global__ __launch_bounds__(256, 1) void argmin_mma_kernel(const int* __restrict__ host) {
    extern __shared__ char smem[];
    const uint32_t sb  = smem_to_u32(smem);
    int*   hc  = (int*)(smem + SM_HC);
    float* sc  = (float*)(smem + SM_SC);
    unsigned long long* red = (unsigned long long*)(smem + SM_RED);

    const int tid  = threadIdx.x;
    const int lane = tid & 31;
    const int wid  = tid >> 5;
    const int warp_m = wid & 3;
    const int warp_n = wid >> 2;
    const int row_base = blockIdx.x * BM;
    const int col_cta  = blockIdx.y * (NSUB * BN);

    // ---- per-thread row metadata (4 rows: mt in {0,1}, h in {0,1}) ----
    int   hr[2][2];
    float sr[2][2];
#pragma unroll
    for (int mt = 0; mt < 2; ++mt)
#pragma unroll
        for (int h = 0; h < 2; ++h) {
            int r = row_base + warp_m * 32 + mt * 16 + h * 8 + (lane >> 2);
            hr[mt][h] = host[r];
            sr[mt][h] = g_sq[r];
        }

    // ---- prologue: stage full A (hi+lo, 16 chunks of [128 x 32]) ----
#pragma unroll
    for (int ch = 0; ch < 16; ++ch) {
        const uint32_t* sbase = (ch < 8) ? g_hi : g_lo;
#pragma unroll
        for (int it = 0; it < 2; ++it) {
            int idx = it * 256 + tid;
            int r = idx >> 2, c = idx & 3;
            const uint32_t* src = sbase + (size_t)(row_base + r) * (D / 2) + (ch & 7) * 16 + c * 4;
            CP_ASYNC16(sb + SM_A + ch * 8192 + swz(r, c), src);
        }
    }
    // B chunk 0 (global chunk g=0 -> stage 0)
#pragma unroll
    for (int hl = 0; hl < 2; ++hl) {
        const uint32_t* sbase = hl ? g_lo : g_hi;
#pragma unroll
        for (int it = 0; it < 2; ++it) {
            int idx = it * 256 + tid;
            int r = idx >> 2, c = idx & 3;
            const uint32_t* src = sbase + (size_t)(col_cta + r) * (D / 2) + c * 4;
            CP_ASYNC16(sb + SM_B + hl * 8192 + swz(r, c), src);
        }
    }
    CP_COMMIT();

    unsigned long long best = 0xFFFFFFFFFFFFFFFFull;

    // ldmatrix per-thread address components (constant across loop)
    const int a_roff = warp_m * 32 + (lane & 7) + ((lane >> 3) & 1) * 8;
    const int a_koff = (lane >> 4);                 // k-halves
    const int b_roff = warp_n * 64 + (lane & 7) + (lane >> 4) * 8;
    const int b_koff = ((lane >> 3) & 1);

    for (int s = 0; s < NSUB; ++s) {
        const int col0 = col_cta + s * BN;
        if (tid < 128) {
            hc[tid] = host[col0 + tid];
            sc[tid] = g_sq[col0 + tid];
        }

        float acc[2][8][4];
#pragma unroll
        for (int mt = 0; mt < 2; ++mt)
#pragma unroll
            for (int nt = 0; nt < 8; ++nt)
#pragma unroll
                for (int e = 0; e < 4; ++e) acc[mt][nt][e] = 0.f;

        for (int kc = 0; kc < 8; ++kc) {
            const int g = s * 8 + kc;
            CP_WAIT0();
            __syncthreads();

            // prefetch next B chunk into stage (g+1)&1
            const int gn = g + 1;
            if (gn < NSUB * 8) {
                const int col0n = col_cta + (gn >> 3) * BN;
                const int kcn   = gn & 7;
#pragma unroll
                for (int hl = 0; hl < 2; ++hl) {
                    const uint32_t* sbase = hl ? g_lo : g_hi;
#pragma unroll
                    for (int it = 0; it < 2; ++it) {
                        int idx = it * 256 + tid;
                        int r = idx >> 2, c = idx & 3;
                        const uint32_t* src = sbase + (size_t)(col0n + r) * (D / 2) + kcn * 16 + c * 4;
                        CP_ASYNC16(sb + SM_B + ((gn & 1) * 2 + hl) * 8192 + swz(r, c), src);
                    }
                }
            }
            CP_COMMIT();

            // compute 2 k16-steps on stage g&1, A chunk kc
            const uint32_t aHi = sb + SM_A + kc * 8192;
            const uint32_t aLo = aHi + 8 * 8192;
            const uint32_t bHi = sb + SM_B + ((g & 1) * 2 + 0) * 8192;
            const uint32_t bLo = sb + SM_B + ((g & 1) * 2 + 1) * 8192;

#pragma unroll
            for (int ks = 0; ks < 2; ++ks) {
                uint32_t ah[2][4], al[2][4];
#pragma unroll
                for (int mt = 0; mt < 2; ++mt) {
                    uint32_t off = swz(a_roff + mt * 16, 2 * ks + a_koff);
                    LDSM_X4(ah[mt], aHi + off);
                    LDSM_X4(al[mt], aLo + off);
                }
                uint32_t bh[16], bl[16];
#pragma unroll
                for (int p = 0; p < 4; ++p) {
                    uint32_t off = swz(b_roff + p * 16, 2 * ks + b_koff);
                    LDSM_X4(&bh[p * 4], bHi + off);
                    LDSM_X4(&bl[p * 4], bLo + off);
                }
#pragma unroll
                for (int mt = 0; mt < 2; ++mt)
#pragma unroll
                    for (int nt = 0; nt < 8; ++nt) {
                        const int bi = (nt >> 1) * 4 + (nt & 1) * 2;
                        MMA16816(acc[mt][nt], ah[mt], bh[bi], bh[bi + 1]);  // hi*hi
                        MMA16816(acc[mt][nt], ah[mt], bl[bi], bl[bi + 1]);  // hi*lo
                        MMA16816(acc[mt][nt], al[mt], bh[bi], bh[bi + 1]);  // lo*hi
                    }
            }
        }

        // ---- epilogue: masked packed argmin over this 128x128 tile ----
#pragma unroll
        for (int mt = 0; mt < 2; ++mt)
#pragma unroll
            for (int h = 0; h < 2; ++h) {
                unsigned long long key = 0xFFFFFFFFFFFFFFFFull;
                const int   hrow = hr[mt][h];
                const float srow = sr[mt][h];
#pragma unroll
                for (int nt = 0; nt < 8; ++nt)
#pragma unroll
                    for (int e = 0; e < 2; ++e) {
                        const int cl = warp_n * 64 + nt * 8 + (lane & 3) * 2 + e;
                        float d2 = fmaxf(fmaf(-2.0f, acc[mt][nt][h * 2 + e], srow + sc[cl]), 0.0f);
                        if (hc[cl] != hrow) {
                            unsigned long long k =
                                ((unsigned long long)__float_as_uint(d2) << 32) |
                                (unsigned int)(col0 + cl);
                            key = umin64(key, k);
                        }
                    }
                key = umin64(key, shfl_xor_u64(key, 1));
                key = umin64(key, shfl_xor_u64(key, 2));
                if ((lane & 3) == 0) {
                    int rl = warp_m * 32 + mt * 16 + h * 8 + (lane >> 2);
                    red[rl * 2 + warp_n] = key;
                }
            }
        __syncthreads();
        if (tid < 128) best = umin64(best, umin64(red[tid * 2], red[tid * 2 + 1]));
        __syncthreads();
    }

    if (tid < 128) g_pkey[blockIdx.y * N + row_base + tid] = best;
}

// ============================================================================
// Finalize: min over 16 chunk partials per row, gather e_actv[idx].
// ============================================================================
__global__ void finalize_kernel(const float* __restrict__ A, float* __restrict__ out_an) {
    const int row = blockIdx.x;
    unsigned long long m = 0xFFFFFFFFFFFFFFFFull;
#pragma unroll
    for (int p = 0; p < CCHUNKS; ++p) {
        unsigned long long v = g_pkey[p * N + row];
        if (v < m) m = v;
    }
    const int idx = (int)(m & 0xFFFFFFFFu);
    const float4* src = (const float4*)(A + (size_t)idx * D);
    float4* dst = (float4*)(out_an + (size_t)row * D);
    dst[threadIdx.x] = src[threadIdx.x];
}

// ============================================================================
extern "C" void kernel_launch(void* const* d_in, const int* in_sizes, int n_in,
                              void* d_out, int out_size) {
    const float* e_actv = (const float*)d_in[0];
    const float* e_ap   = (const float*)d_in[1];
    const int*   host   = (const int*)d_in[2];
    float* out = (float*)d_out;
    const size_t nd = (size_t)N * D;

    cudaMemcpyAsync(out,      e_actv, nd * sizeof(float), cudaMemcpyDeviceToDevice, 0);
    cudaMemcpyAsync(out + nd, e_ap,   nd * sizeof(float), cudaMemcpyDeviceToDevice, 0);

    cudaFuncSetAttribute(argmin_mma_kernel, cudaFuncAttributeMaxDynamicSharedMemorySize, SM_TOTAL);

    split_norms_kernel<<<N / 8, 256>>>(e_actv);
    argmin_mma_kernel<<<dim3(N / BM, CCHUNKS), 256, SM_TOTAL>>>(host);
    finalize_kernel<<<N, 64>>>(e_actv, out + 2 * nd);
}

// round 5
// speedup vs baseline: 4.6494x; 1.4114x over previous
#include <cuda_runtime.h>
#include <cuda_bf16.h>
#include <cstdint>

#define N 8192
#define D 256
#define BM 128
#define BN 128
#define NTILES 64           // N / BM
#define NBLOCKS (NTILES * (NTILES + 1) / 2)   // 2080 upper-triangular tiles

// ---- smem layout (bytes): 2 stages x (Ahi,Alo,Bhi,Blo) x 8KB ----
#define SM_STG   0
#define STG_SZ   32768
#define SM_HC    (2 * STG_SZ)          // 128 ints
#define SM_SC    (SM_HC + 512)         // 128 floats
#define SM_RED   (SM_SC + 512)         // 128 * 2 u64
#define SM_TOTAL (SM_RED + 2048)       // 68608 bytes

// ---- device scratch (no allocation) ----
__device__ float g_sq[N];
__device__ __align__(16) uint32_t g_hi[N * (D / 2)];   // bf16x2 packed
__device__ __align__(16) uint32_t g_lo[N * (D / 2)];
__device__ unsigned long long g_key[N];

// ============================ PTX helpers ============================
__device__ __forceinline__ uint32_t smem_to_u32(const void* p) {
    uint32_t a;
    asm("{ .reg .u64 t; cvta.to.shared.u64 t, %1; cvt.u32.u64 %0, t; }" : "=r"(a) : "l"(p));
    return a;
}
#define CP_ASYNC16(dst, src) \
    asm volatile("cp.async.cg.shared.global [%0], [%1], 16;" :: "r"(dst), "l"(src))
#define CP_COMMIT() asm volatile("cp.async.commit_group;" ::: "memory")
#define CP_WAIT0()  asm volatile("cp.async.wait_group 0;" ::: "memory")
#define CP_WAIT1()  asm volatile("cp.async.wait_group 1;" ::: "memory")

#define LDSM_X4(r, addr) \
    asm volatile("ldmatrix.sync.aligned.m8n8.x4.shared.b16 {%0,%1,%2,%3}, [%4];" \
        : "=r"((r)[0]), "=r"((r)[1]), "=r"((r)[2]), "=r"((r)[3]) : "r"(addr))

#define MMA16816(c, a, b0, b1) \
    asm volatile("mma.sync.aligned.m16n8k16.row.col.f32.bf16.bf16.f32 " \
        "{%0,%1,%2,%3}, {%4,%5,%6,%7}, {%8,%9}, {%0,%1,%2,%3};" \
        : "+f"((c)[0]), "+f"((c)[1]), "+f"((c)[2]), "+f"((c)[3]) \
        : "r"((a)[0]), "r"((a)[1]), "r"((a)[2]), "r"((a)[3]), "r"(b0), "r"(b1))

// 64B-row chunk swizzle: 8 consecutive rows hit 8 distinct 16B bank-groups.
__device__ __forceinline__ uint32_t swz(int r, int c16) {
    return (uint32_t)(r * 64 + ((c16 ^ ((r >> 1) & 3)) << 4));
}
__device__ __forceinline__ unsigned long long shfl_xor_u64(unsigned long long v, int m) {
    uint32_t lo = (uint32_t)v, hi = (uint32_t)(v >> 32);
    lo = __shfl_xor_sync(0xffffffffu, lo, m);
    hi = __shfl_xor_sync(0xffffffffu, hi, m);
    return ((unsigned long long)hi << 32) | lo;
}
__device__ __forceinline__ unsigned long long umin64(unsigned long long a, unsigned long long b) {
    return a < b ? a : b;
}

// ============================================================================
__global__ void init_keys_kernel() {
    g_key[blockIdx.x * 1024 + threadIdx.x] = 0xFFFFFFFFFFFFFFFFull;
}

// ============================================================================
// Split A -> bf16 hi/lo + row norms. One warp per row.
// ============================================================================
__global__ void split_norms_kernel(const float* __restrict__ A) {
    int row  = blockIdx.x * 8 + (threadIdx.x >> 5);
    int lane = threadIdx.x & 31;
    const float4* a = (const float4*)(A + (size_t)row * D);
    float s = 0.f;
#pragma unroll
    for (int q = 0; q < 2; ++q) {
        float4 v = a[lane + 32 * q];
        s += v.x * v.x + v.y * v.y + v.z * v.z + v.w * v.w;
        __nv_bfloat162 h0 = __floats2bfloat162_rn(v.x, v.y);
        __nv_bfloat162 h1 = __floats2bfloat162_rn(v.z, v.w);
        float lx = v.x - __bfloat162float(h0.x);
        float ly = v.y - __bfloat162float(h0.y);
        float lz = v.z - __bfloat162float(h1.x);
        float lw = v.w - __bfloat162float(h1.y);
        __nv_bfloat162 l0 = __floats2bfloat162_rn(lx, ly);
        __nv_bfloat162 l1 = __floats2bfloat162_rn(lz, lw);
        uint2 hv = make_uint2(*reinterpret_cast<uint32_t*>(&h0), *reinterpret_cast<uint32_t*>(&h1));
        uint2 lv = make_uint2(*reinterpret_cast<uint32_t*>(&l0), *reinterpret_cast<uint32_t*>(&l1));
        size_t w = (size_t)row * (D / 2) + (lane + 32 * q) * 2;
        *(uint2*)(g_hi + w) = hv;
        *(uint2*)(g_lo + w) = lv;
    }
#pragma unroll
    for (int o = 16; o; o >>= 1) s += __shfl_xor_sync(0xffffffffu, s, o);
    if (lane == 0) g_sq[row] = s;
}

// ============================================================================
// Symmetric bf16x3 Gram tiles (upper-triangular only) + dual-direction argmin.
// Block 256 = 8 warps (warp_m 0..3, warp_n 0..1); warp tile 32x64.
// ============================================================================
__global__ __launch_bounds__(256, 1) void argmin_mma_kernel(const int* __restrict__ host) {
    extern __shared__ char smem[];
    const uint32_t sb  = smem_to_u32(smem);
    int*   hc  = (int*)(smem + SM_HC);
    float* sc  = (float*)(smem + SM_SC);
    unsigned long long* red = (unsigned long long*)(smem + SM_RED);

    const int tid  = threadIdx.x;
    const int lane = tid & 31;
    const int wid  = tid >> 5;
    const int warp_m = wid & 3;
    const int warp_n = wid >> 2;

    // ---- triangular tile decode: bid -> (ti, tj), tj >= ti ----
    const int bid = blockIdx.x;
    int ti = (int)(64.5f - sqrtf(64.5f * 64.5f - 2.0f * (float)bid));
    // offset(t) = t*64 - t*(t-1)/2
    while (ti > 0  && (ti * 64 - ti * (ti - 1) / 2) > bid) --ti;
    while (((ti + 1) * 64 - (ti + 1) * ti / 2) <= bid) ++ti;
    const int tj = ti + (bid - (ti * 64 - ti * (ti - 1) / 2));
    const int row_base = ti * BM;
    const int col_base = tj * BM;

    // ---- per-thread row metadata (4 rows: mt, h) ----
    int   hr[2][2];
    float sr[2][2];
#pragma unroll
    for (int mt = 0; mt < 2; ++mt)
#pragma unroll
        for (int h = 0; h < 2; ++h) {
            int r = row_base + warp_m * 32 + mt * 16 + h * 8 + (lane >> 2);
            hr[mt][h] = host[r];
            sr[mt][h] = g_sq[r];
        }
    if (tid < 128) {
        hc[tid] = host[col_base + tid];
        sc[tid] = g_sq[col_base + tid];
    }

    // ---- chunk loader: chunk kc (k=32 slice) -> stage st ----
    auto load_chunk = [&](int kc, int st) {
        const uint32_t stg = sb + SM_STG + st * STG_SZ;
#pragma unroll
        for (int hl = 0; hl < 2; ++hl) {
            const uint32_t* sbase = hl ? g_lo : g_hi;
#pragma unroll
            for (int it = 0; it < 2; ++it) {
                int idx = it * 256 + tid;
                int r = idx >> 2, c = idx & 3;
                uint32_t sw = swz(r, c);
                const uint32_t* srcA = sbase + (size_t)(row_base + r) * (D / 2) + kc * 16 + c * 4;
                const uint32_t* srcB = sbase + (size_t)(col_base + r) * (D / 2) + kc * 16 + c * 4;
                CP_ASYNC16(stg + hl * 8192 + sw, srcA);
                CP_ASYNC16(stg + 16384 + hl * 8192 + sw, srcB);
            }
        }
    };

    load_chunk(0, 0);
    CP_COMMIT();

    float acc[2][8][4];
#pragma unroll
    for (int mt = 0; mt < 2; ++mt)
#pragma unroll
        for (int nt = 0; nt < 8; ++nt)
#pragma unroll
            for (int e = 0; e < 4; ++e) acc[mt][nt][e] = 0.f;

    const int a_roff = warp_m * 32 + (lane & 7) + ((lane >> 3) & 1) * 8;
    const int a_koff = (lane >> 4);
    const int b_roff = warp_n * 64 + (lane & 7) + (lane >> 4) * 8;
    const int b_koff = ((lane >> 3) & 1);

    for (int kc = 0; kc < 8; ++kc) {
        if (kc < 7) {
            load_chunk(kc + 1, (kc + 1) & 1);
            CP_COMMIT();
            CP_WAIT1();
        } else {
            CP_WAIT0();
        }
        __syncthreads();

        const uint32_t stg = sb + SM_STG + (kc & 1) * STG_SZ;
        const uint32_t aHi = stg, aLo = stg + 8192;
        const uint32_t bHi = stg + 16384, bLo = stg + 24576;

#pragma unroll
        for (int ks = 0; ks < 2; ++ks) {
            uint32_t ah[2][4], al[2][4];
#pragma unroll
            for (int mt = 0; mt < 2; ++mt) {
                uint32_t off = swz(a_roff + mt * 16, 2 * ks + a_koff);
                LDSM_X4(ah[mt], aHi + off);
                LDSM_X4(al[mt], aLo + off);
            }
            uint32_t bh[16], bl[16];
#pragma unroll
            for (int p = 0; p < 4; ++p) {
                uint32_t off = swz(b_roff + p * 16, 2 * ks + b_koff);
                LDSM_X4(&bh[p * 4], bHi + off);
                LDSM_X4(&bl[p * 4], bLo + off);
            }
#pragma unroll
            for (int mt = 0; mt < 2; ++mt)
#pragma unroll
                for (int nt = 0; nt < 8; ++nt) {
                    const int bi = (nt >> 1) * 4 + (nt & 1) * 2;
                    MMA16816(acc[mt][nt], ah[mt], bh[bi], bh[bi + 1]);  // hi*hi
                    MMA16816(acc[mt][nt], ah[mt], bl[bi], bl[bi + 1]);  // hi*lo
                    MMA16816(acc[mt][nt], al[mt], bh[bi], bh[bi + 1]);  // lo*hi
                }
        }
        __syncthreads();
    }

    // ======================= epilogue: both directions =======================
    // --- row direction: for each of this thread's 4 rows, min over its 16 cols ---
#pragma unroll
    for (int mt = 0; mt < 2; ++mt)
#pragma unroll
        for (int h = 0; h < 2; ++h) {
            unsigned long long key = 0xFFFFFFFFFFFFFFFFull;
            const int   hrow = hr[mt][h];
            const float srow = sr[mt][h];
#pragma unroll
            for (int nt = 0; nt < 8; ++nt)
#pragma unroll
                for (int e = 0; e < 2; ++e) {
                    const int cl = warp_n * 64 + nt * 8 + (lane & 3) * 2 + e;
                    float d2 = fmaxf(fmaf(-2.0f, acc[mt][nt][h * 2 + e], srow + sc[cl]), 0.0f);
                    if (hc[cl] != hrow) {
                        unsigned long long k =
                            ((unsigned long long)__float_as_uint(d2) << 32) |
                            (unsigned int)(col_base + cl);
                        key = umin64(key, k);
                    }
                }
            key = umin64(key, shfl_xor_u64(key, 1));
            key = umin64(key, shfl_xor_u64(key, 2));
            if ((lane & 3) == 0) {
                int rl = warp_m * 32 + mt * 16 + h * 8 + (lane >> 2);
                red[rl * 2 + warp_n] = key;
            }
        }
    __syncthreads();
    if (tid < 128) {
        unsigned long long k = umin64(red[tid * 2], red[tid * 2 + 1]);
        if (k != 0xFFFFFFFFFFFFFFFFull) atomicMin(&g_key[row_base + tid], k);
    }

    // --- col direction: for each of this thread's 16 cols, min over rows (idx=row) ---
#pragma unroll
    for (int nt = 0; nt < 8; ++nt)
#pragma unroll
        for (int e = 0; e < 2; ++e) {
            const int cl = warp_n * 64 + nt * 8 + (lane & 3) * 2 + e;
            const int   hcol = hc[cl];
            const float scol = sc[cl];
            unsigned long long key = 0xFFFFFFFFFFFFFFFFull;
#pragma unroll
            for (int mt = 0; mt < 2; ++mt)
#pragma unroll
                for (int h = 0; h < 2; ++h) {
                    float d2 = fmaxf(fmaf(-2.0f, acc[mt][nt][h * 2 + e], sr[mt][h] + scol), 0.0f);
                    if (hr[mt][h] != hcol) {
                        int r = row_base + warp_m * 32 + mt * 16 + h * 8 + (lane >> 2);
                        unsigned long long k =
                            ((unsigned long long)__float_as_uint(d2) << 32) | (unsigned int)r;
                        key = umin64(key, k);
                    }
                }
            // reduce across the 8 row-groups (lanes sharing lane&3)
            key = umin64(key, shfl_xor_u64(key, 4));
            key = umin64(key, shfl_xor_u64(key, 8));
            key = umin64(key, shfl_xor_u64(key, 16));
            if ((lane >> 2) == 0 && key != 0xFFFFFFFFFFFFFFFFull)
                atomicMin(&g_key[col_base + cl], key);
        }
}

// ============================================================================
// Finalize: gather e_actv[idx] per row.
// ============================================================================
__global__ void finalize_kernel(const float* __restrict__ A, float* __restrict__ out_an) {
    const int row = blockIdx.x;
    const int idx = (int)(g_key[row] & 0xFFFFFFFFu);
    const float4* src = (const float4*)(A + (size_t)idx * D);
    float4* dst = (float4*)(out_an + (size_t)row * D);
    dst[threadIdx.x] = src[threadIdx.x];
}

// ============================================================================
extern "C" void kernel_launch(void* const* d_in, const int* in_sizes, int n_in,
                              void* d_out, int out_size) {
    const float* e_actv = (const float*)d_in[0];
    const float* e_ap   = (const float*)d_in[1];
    const int*   host   = (const int*)d_in[2];
    float* out = (float*)d_out;
    const size_t nd = (size_t)N * D;

    cudaMemcpyAsync(out,      e_actv, nd * sizeof(float), cudaMemcpyDeviceToDevice, 0);
    cudaMemcpyAsync(out + nd, e_ap,   nd * sizeof(float), cudaMemcpyDeviceToDevice, 0);

    cudaFuncSetAttribute(argmin_mma_kernel, cudaFuncAttributeMaxDynamicSharedMemorySize, SM_TOTAL);

    init_keys_kernel<<<N / 1024, 1024>>>();
    split_norms_kernel<<<N / 8, 256>>>(e_actv);
    argmin_mma_kernel<<<NBLOCKS, 256, SM_TOTAL>>>(host);
    finalize_kernel<<<N, 64>>>(e_actv, out + 2 * nd);
}

// round 6
// speedup vs baseline: 5.8945x; 1.2678x over previous
#include <cuda_runtime.h>
#include <cuda_bf16.h>
#include <cstdint>

#define N 8192
#define D 256
#define BM 128
#define BN 128
#define NTILES 64
#define NBLOCKS (NTILES * (NTILES + 1) / 2)   // 2080 upper-triangular tiles

// ---- smem layout (bytes): 2 stages x (Ahi,Alo,Bhi,Blo) x 8KB ----
#define SM_STG   0
#define STG_SZ   32768
#define SM_HC    (2 * STG_SZ)
#define SM_SC    (SM_HC + 512)
#define SM_RED   (SM_SC + 512)
#define SM_TOTAL (SM_RED + 2048)       // 68608 bytes

// ---- device scratch (no allocation) ----
__device__ float g_sq[N];
__device__ __align__(16) uint32_t g_hi[N * (D / 2)];
__device__ __align__(16) uint32_t g_lo[N * (D / 2)];
__device__ unsigned long long g_key[N];

// ============================ PTX helpers ============================
__device__ __forceinline__ uint32_t smem_to_u32(const void* p) {
    uint32_t a;
    asm("{ .reg .u64 t; cvta.to.shared.u64 t, %1; cvt.u32.u64 %0, t; }" : "=r"(a) : "l"(p));
    return a;
}
#define CP_ASYNC16(dst, src) \
    asm volatile("cp.async.cg.shared.global [%0], [%1], 16;" :: "r"(dst), "l"(src))
#define CP_COMMIT() asm volatile("cp.async.commit_group;" ::: "memory")
#define CP_WAIT0()  asm volatile("cp.async.wait_group 0;" ::: "memory")
#define CP_WAIT1()  asm volatile("cp.async.wait_group 1;" ::: "memory")

#define LDSM_X4(r, addr) \
    asm volatile("ldmatrix.sync.aligned.m8n8.x4.shared.b16 {%0,%1,%2,%3}, [%4];" \
        : "=r"((r)[0]), "=r"((r)[1]), "=r"((r)[2]), "=r"((r)[3]) : "r"(addr))

// non-volatile: outputs fully constrain ordering; lets the compiler schedule
#define MMA16816(c, a, b0, b1) \
    asm("mma.sync.aligned.m16n8k16.row.col.f32.bf16.bf16.f32 " \
        "{%0,%1,%2,%3}, {%4,%5,%6,%7}, {%8,%9}, {%0,%1,%2,%3};" \
        : "+f"((c)[0]), "+f"((c)[1]), "+f"((c)[2]), "+f"((c)[3]) \
        : "r"((a)[0]), "r"((a)[1]), "r"((a)[2]), "r"((a)[3]), "r"(b0), "r"(b1))

__device__ __forceinline__ uint32_t swz(int r, int c16) {
    return (uint32_t)(r * 64 + ((c16 ^ ((r >> 1) & 3)) << 4));
}
__device__ __forceinline__ unsigned long long shfl_xor_u64(unsigned long long v, int m) {
    uint32_t lo = (uint32_t)v, hi = (uint32_t)(v >> 32);
    lo = __shfl_xor_sync(0xffffffffu, lo, m);
    hi = __shfl_xor_sync(0xffffffffu, hi, m);
    return ((unsigned long long)hi << 32) | lo;
}
__device__ __forceinline__ unsigned long long umin64(unsigned long long a, unsigned long long b) {
    return a < b ? a : b;
}

// ============================================================================
// Split A -> bf16 hi/lo + row norms + init keys. One warp per row.
// ============================================================================
__global__ void split_norms_kernel(const float* __restrict__ A) {
    int gid = blockIdx.x * 256 + threadIdx.x;
    if (gid < N) g_key[gid] = 0xFFFFFFFFFFFFFFFFull;

    int row  = blockIdx.x * 8 + (threadIdx.x >> 5);
    int lane = threadIdx.x & 31;
    const float4* a = (const float4*)(A + (size_t)row * D);
    float s = 0.f;
#pragma unroll
    for (int q = 0; q < 2; ++q) {
        float4 v = a[lane + 32 * q];
        s += v.x * v.x + v.y * v.y + v.z * v.z + v.w * v.w;
        __nv_bfloat162 h0 = __floats2bfloat162_rn(v.x, v.y);
        __nv_bfloat162 h1 = __floats2bfloat162_rn(v.z, v.w);
        float lx = v.x - __bfloat162float(h0.x);
        float ly = v.y - __bfloat162float(h0.y);
        float lz = v.z - __bfloat162float(h1.x);
        float lw = v.w - __bfloat162float(h1.y);
        __nv_bfloat162 l0 = __floats2bfloat162_rn(lx, ly);
        __nv_bfloat162 l1 = __floats2bfloat162_rn(lz, lw);
        uint2 hv = make_uint2(*reinterpret_cast<uint32_t*>(&h0), *reinterpret_cast<uint32_t*>(&h1));
        uint2 lv = make_uint2(*reinterpret_cast<uint32_t*>(&l0), *reinterpret_cast<uint32_t*>(&l1));
        size_t w = (size_t)row * (D / 2) + (lane + 32 * q) * 2;
        *(uint2*)(g_hi + w) = hv;
        *(uint2*)(g_lo + w) = lv;
    }
#pragma unroll
    for (int o = 16; o; o >>= 1) s += __shfl_xor_sync(0xffffffffu, s, o);
    if (lane == 0) g_sq[row] = s;
}

// ============================================================================
// Symmetric bf16x3 Gram tiles (upper-triangular) + dual-direction argmin.
// Block 256 = 8 warps (warp_m 0..3, warp_n 0..1); warp tile 32x64. occ=2.
// ============================================================================
__global__ __launch_bounds__(256, 2) void argmin_mma_kernel(const int* __restrict__ host) {
    extern __shared__ char smem[];
    const uint32_t sb  = smem_to_u32(smem);
    int*   hc  = (int*)(smem + SM_HC);
    float* sc  = (float*)(smem + SM_SC);
    unsigned long long* red = (unsigned long long*)(smem + SM_RED);

    const int tid  = threadIdx.x;
    const int lane = tid & 31;
    const int wid  = tid >> 5;
    const int warp_m = wid & 3;
    const int warp_n = wid >> 2;

    // ---- triangular tile decode: bid -> (ti, tj), tj >= ti ----
    const int bid = blockIdx.x;
    int ti = (int)(64.5f - sqrtf(64.5f * 64.5f - 2.0f * (float)bid));
    while (ti > 0  && (ti * 64 - ti * (ti - 1) / 2) > bid) --ti;
    while (((ti + 1) * 64 - (ti + 1) * ti / 2) <= bid) ++ti;
    const int tj = ti + (bid - (ti * 64 - ti * (ti - 1) / 2));
    const int row_base = ti * BM;
    const int col_base = tj * BM;

    if (tid < 128) {
        hc[tid] = host[col_base + tid];
        sc[tid] = g_sq[col_base + tid];
    }

    auto load_chunk = [&](int kc, int st) {
        const uint32_t stg = sb + SM_STG + st * STG_SZ;
#pragma unroll
        for (int hl = 0; hl < 2; ++hl) {
            const uint32_t* sbase = hl ? g_lo : g_hi;
#pragma unroll
            for (int it = 0; it < 2; ++it) {
                int idx = it * 256 + tid;
                int r = idx >> 2, c = idx & 3;
                uint32_t sw = swz(r, c);
                const uint32_t* srcA = sbase + (size_t)(row_base + r) * (D / 2) + kc * 16 + c * 4;
                const uint32_t* srcB = sbase + (size_t)(col_base + r) * (D / 2) + kc * 16 + c * 4;
                CP_ASYNC16(stg + hl * 8192 + sw, srcA);
                CP_ASYNC16(stg + 16384 + hl * 8192 + sw, srcB);
            }
        }
    };

    load_chunk(0, 0);
    CP_COMMIT();

    float acc[2][8][4];
#pragma unroll
    for (int mt = 0; mt < 2; ++mt)
#pragma unroll
        for (int nt = 0; nt < 8; ++nt)
#pragma unroll
            for (int e = 0; e < 4; ++e) acc[mt][nt][e] = 0.f;

    const int a_roff = warp_m * 32 + (lane & 7) + ((lane >> 3) & 1) * 8;
    const int a_koff = (lane >> 4);
    const int b_roff = warp_n * 64 + (lane & 7) + (lane >> 4) * 8;
    const int b_koff = ((lane >> 3) & 1);

    for (int kc = 0; kc < 8; ++kc) {
        if (kc < 7) {
            load_chunk(kc + 1, (kc + 1) & 1);
            CP_COMMIT();
            CP_WAIT1();
        } else {
            CP_WAIT0();
        }
        __syncthreads();

        const uint32_t stg = sb + SM_STG + (kc & 1) * STG_SZ;
        const uint32_t aHi = stg, aLo = stg + 8192;
        const uint32_t bHi = stg + 16384, bLo = stg + 24576;

#pragma unroll
        for (int ks = 0; ks < 2; ++ks) {
            uint32_t ah[2][4], al[2][4];
#pragma unroll
            for (int mt = 0; mt < 2; ++mt) {
                uint32_t off = swz(a_roff + mt * 16, 2 * ks + a_koff);
                LDSM_X4(ah[mt], aHi + off);
                LDSM_X4(al[mt], aLo + off);
            }
            uint32_t b0[16], b1[16];
#pragma unroll
            for (int p = 0; p < 4; ++p)
                LDSM_X4(&b0[p * 4], bHi + swz(b_roff + p * 16, 2 * ks + b_koff));
            // pass 1: hi*hi  (16 independent HMMAs)
#pragma unroll
            for (int mt = 0; mt < 2; ++mt)
#pragma unroll
                for (int nt = 0; nt < 8; ++nt) {
                    const int bi = (nt >> 1) * 4 + (nt & 1) * 2;
                    MMA16816(acc[mt][nt], ah[mt], b0[bi], b0[bi + 1]);
                }
#pragma unroll
            for (int p = 0; p < 4; ++p)
                LDSM_X4(&b1[p * 4], bLo + swz(b_roff + p * 16, 2 * ks + b_koff));
            // pass 2: lo*hi
#pragma unroll
            for (int mt = 0; mt < 2; ++mt)
#pragma unroll
                for (int nt = 0; nt < 8; ++nt) {
                    const int bi = (nt >> 1) * 4 + (nt & 1) * 2;
                    MMA16816(acc[mt][nt], al[mt], b0[bi], b0[bi + 1]);
                }
            // pass 3: hi*lo
#pragma unroll
            for (int mt = 0; mt < 2; ++mt)
#pragma unroll
                for (int nt = 0; nt < 8; ++nt) {
                    const int bi = (nt >> 1) * 4 + (nt & 1) * 2;
                    MMA16816(acc[mt][nt], ah[mt], b1[bi], b1[bi + 1]);
                }
        }
        __syncthreads();
    }

    // ======================= epilogue: both directions =======================
    // row metadata loaded here (kept out of the mainloop register budget)
    int   hr[2][2];
    float sr[2][2];
#pragma unroll
    for (int mt = 0; mt < 2; ++mt)
#pragma unroll
        for (int h = 0; h < 2; ++h) {
            int r = row_base + warp_m * 32 + mt * 16 + h * 8 + (lane >> 2);
            hr[mt][h] = host[r];
            sr[mt][h] = g_sq[r];
        }

    // --- row direction ---
#pragma unroll
    for (int mt = 0; mt < 2; ++mt)
#pragma unroll
        for (int h = 0; h < 2; ++h) {
            unsigned long long key = 0xFFFFFFFFFFFFFFFFull;
            const int   hrow = hr[mt][h];
            const float srow = sr[mt][h];
#pragma unroll
            for (int nt = 0; nt < 8; ++nt)
#pragma unroll
                for (int e = 0; e < 2; ++e) {
                    const int cl = warp_n * 64 + nt * 8 + (lane & 3) * 2 + e;
                    float d2 = fmaxf(fmaf(-2.0f, acc[mt][nt][h * 2 + e], srow + sc[cl]), 0.0f);
                    if (hc[cl] != hrow) {
                        unsigned long long k =
                            ((unsigned long long)__float_as_uint(d2) << 32) |
                            (unsigned int)(col_base + cl);
                        key = umin64(key, k);
                    }
                }
            key = umin64(key, shfl_xor_u64(key, 1));
            key = umin64(key, shfl_xor_u64(key, 2));
            if ((lane & 3) == 0) {
                int rl = warp_m * 32 + mt * 16 + h * 8 + (lane >> 2);
                red[rl * 2 + warp_n] = key;
            }
        }
    __syncthreads();
    if (tid < 128) {
        unsigned long long k = umin64(red[tid * 2], red[tid * 2 + 1]);
        if (k != 0xFFFFFFFFFFFFFFFFull) atomicMin(&g_key[row_base + tid], k);
    }

    // --- col direction ---
#pragma unroll
    for (int nt = 0; nt < 8; ++nt)
#pragma unroll
        for (int e = 0; e < 2; ++e) {
            const int cl = warp_n * 64 + nt * 8 + (lane & 3) * 2 + e;
            const int   hcol = hc[cl];
            const float scol = sc[cl];
            unsigned long long key = 0xFFFFFFFFFFFFFFFFull;
#pragma unroll
            for (int mt = 0; mt < 2; ++mt)
#pragma unroll
                for (int h = 0; h < 2; ++h) {
                    float d2 = fmaxf(fmaf(-2.0f, acc[mt][nt][h * 2 + e], sr[mt][h] + scol), 0.0f);
                    if (hr[mt][h] != hcol) {
                        int r = row_base + warp_m * 32 + mt * 16 + h * 8 + (lane >> 2);
                        unsigned long long k =
                            ((unsigned long long)__float_as_uint(d2) << 32) | (unsigned int)r;
                        key = umin64(key, k);
                    }
                }
            key = umin64(key, shfl_xor_u64(key, 4));
            key = umin64(key, shfl_xor_u64(key, 8));
            key = umin64(key, shfl_xor_u64(key, 16));
            if ((lane >> 2) == 0 && key != 0xFFFFFFFFFFFFFFFFull)
                atomicMin(&g_key[col_base + cl], key);
        }
}

// ============================================================================
// Finalize: gather e_actv[idx]; 4 rows per 256-thread block.
// ============================================================================
__global__ void finalize_kernel(const float* __restrict__ A, float* __restrict__ out_an) {
    const int row = blockIdx.x * 4 + (threadIdx.x >> 6);
    const int t   = threadIdx.x & 63;
    const int idx = (int)(g_key[row] & 0xFFFFFFFFu);
    const float4* src = (const float4*)(A + (size_t)idx * D);
    float4* dst = (float4*)(out_an + (size_t)row * D);
    dst[t] = src[t];
}

// ============================================================================
extern "C" void kernel_launch(void* const* d_in, const int* in_sizes, int n_in,
                              void* d_out, int out_size) {
    const float* e_actv = (const float*)d_in[0];
    const float* e_ap   = (const float*)d_in[1];
    const int*   host   = (const int*)d_in[2];
    float* out = (float*)d_out;
    const size_t nd = (size_t)N * D;

    cudaMemcpyAsync(out,      e_actv, nd * sizeof(float), cudaMemcpyDeviceToDevice, 0);
    cudaMemcpyAsync(out + nd, e_ap,   nd * sizeof(float), cudaMemcpyDeviceToDevice, 0);

    cudaFuncSetAttribute(argmin_mma_kernel, cudaFuncAttributeMaxDynamicSharedMemorySize, SM_TOTAL);

    split_norms_kernel<<<N / 8, 256>>>(e_actv);
    argmin_mma_kernel<<<NBLOCKS, 256, SM_TOTAL>>>(host);
    finalize_kernel<<<N / 4, 256>>>(e_actv, out + 2 * nd);
}

// round 7
// speedup vs baseline: 5.9474x; 1.0090x over previous
#include <cuda_runtime.h>
#include <cuda_bf16.h>
#include <cstdint>

#define N 8192
#define D 256
#define BM 128
#define BN 128
#define NTILES 64
#define NBLOCKS (NTILES * (NTILES + 1) / 2)   // 2080 upper-triangular tiles

// ---- smem layout (bytes): 2 stages x (Ahi,Alo,Bhi,Blo) x 8KB ----
#define SM_STG   0
#define STG_SZ   32768
#define SM_HC    (2 * STG_SZ)
#define SM_SC    (SM_HC + 512)
#define SM_RED   (SM_SC + 512)
#define SM_TOTAL (SM_RED + 2048)       // 68608 bytes

// ---- device scratch (no allocation) ----
__device__ float g_sq[N];
__device__ __align__(16) uint32_t g_hi[N * (D / 2)];
__device__ __align__(16) uint32_t g_lo[N * (D / 2)];
__device__ unsigned long long g_key[N];

// ============================ PTX helpers ============================
__device__ __forceinline__ uint32_t smem_to_u32(const void* p) {
    uint32_t a;
    asm("{ .reg .u64 t; cvta.to.shared.u64 t, %1; cvt.u32.u64 %0, t; }" : "=r"(a) : "l"(p));
    return a;
}
#define CP_ASYNC16(dst, src) \
    asm volatile("cp.async.cg.shared.global [%0], [%1], 16;" :: "r"(dst), "l"(src))
#define CP_COMMIT() asm volatile("cp.async.commit_group;" ::: "memory")
#define CP_WAIT0()  asm volatile("cp.async.wait_group 0;" ::: "memory")
#define CP_WAIT1()  asm volatile("cp.async.wait_group 1;" ::: "memory")

#define LDSM_X4(r, addr) \
    asm volatile("ldmatrix.sync.aligned.m8n8.x4.shared.b16 {%0,%1,%2,%3}, [%4];" \
        : "=r"((r)[0]), "=r"((r)[1]), "=r"((r)[2]), "=r"((r)[3]) : "r"(addr))

#define MMA16816(c, a, b0, b1) \
    asm("mma.sync.aligned.m16n8k16.row.col.f32.bf16.bf16.f32 " \
        "{%0,%1,%2,%3}, {%4,%5,%6,%7}, {%8,%9}, {%0,%1,%2,%3};" \
        : "+f"((c)[0]), "+f"((c)[1]), "+f"((c)[2]), "+f"((c)[3]) \
        : "r"((a)[0]), "r"((a)[1]), "r"((a)[2]), "r"((a)[3]), "r"(b0), "r"(b1))

__device__ __forceinline__ uint32_t swz(int r, int c16) {
    return (uint32_t)(r * 64 + ((c16 ^ ((r >> 1) & 3)) << 4));
}
__device__ __forceinline__ unsigned long long shfl_xor_u64(unsigned long long v, int m) {
    uint32_t lo = (uint32_t)v, hi = (uint32_t)(v >> 32);
    lo = __shfl_xor_sync(0xffffffffu, lo, m);
    hi = __shfl_xor_sync(0xffffffffu, hi, m);
    return ((unsigned long long)hi << 32) | lo;
}
__device__ __forceinline__ unsigned long long umin64(unsigned long long a, unsigned long long b) {
    return a < b ? a : b;
}

// ============================================================================
// Fused prep: copy e_actv & e_ap to output, split A -> bf16 hi/lo, row norms,
// init keys. 8 rows per 256-thread block (one warp per row for A work).
// ============================================================================
__global__ void prep_kernel(const float* __restrict__ A, const float* __restrict__ P,
                            float* __restrict__ out) {
    const size_t nd = (size_t)N * D;
    int gid = blockIdx.x * 256 + threadIdx.x;
    if (gid < N) g_key[gid] = 0xFFFFFFFFFFFFFFFFull;

    // copy 8 rows of e_ap (512 float4 per block, 2 per thread)
    {
        const float4* src = (const float4*)(P + (size_t)blockIdx.x * 8 * D);
        float4*       dst = (float4*)(out + nd + (size_t)blockIdx.x * 8 * D);
        dst[threadIdx.x]       = src[threadIdx.x];
        dst[threadIdx.x + 256] = src[threadIdx.x + 256];
    }

    int row  = blockIdx.x * 8 + (threadIdx.x >> 5);
    int lane = threadIdx.x & 31;
    const float4* a  = (const float4*)(A + (size_t)row * D);
    float4*       oa = (float4*)(out + (size_t)row * D);
    float s = 0.f;
#pragma unroll
    for (int q = 0; q < 2; ++q) {
        float4 v = a[lane + 32 * q];
        oa[lane + 32 * q] = v;                        // e_actv copy
        s += v.x * v.x + v.y * v.y + v.z * v.z + v.w * v.w;
        __nv_bfloat162 h0 = __floats2bfloat162_rn(v.x, v.y);
        __nv_bfloat162 h1 = __floats2bfloat162_rn(v.z, v.w);
        float lx = v.x - __bfloat162float(h0.x);
        float ly = v.y - __bfloat162float(h0.y);
        float lz = v.z - __bfloat162float(h1.x);
        float lw = v.w - __bfloat162float(h1.y);
        __nv_bfloat162 l0 = __floats2bfloat162_rn(lx, ly);
        __nv_bfloat162 l1 = __floats2bfloat162_rn(lz, lw);
        uint2 hv = make_uint2(*reinterpret_cast<uint32_t*>(&h0), *reinterpret_cast<uint32_t*>(&h1));
        uint2 lv = make_uint2(*reinterpret_cast<uint32_t*>(&l0), *reinterpret_cast<uint32_t*>(&l1));
        size_t w = (size_t)row * (D / 2) + (lane + 32 * q) * 2;
        *(uint2*)(g_hi + w) = hv;
        *(uint2*)(g_lo + w) = lv;
    }
#pragma unroll
    for (int o = 16; o; o >>= 1) s += __shfl_xor_sync(0xffffffffu, s, o);
    if (lane == 0) g_sq[row] = s;
}

// ============================================================================
// Symmetric bf16x3 Gram tiles (upper-triangular) + dual-direction argmin.
// Block 256 = 8 warps (warp_m 0..3, warp_n 0..1); warp tile 32x64. occ=2.
// ============================================================================
__global__ __launch_bounds__(256, 2) void argmin_mma_kernel(const int* __restrict__ host) {
    extern __shared__ char smem[];
    const uint32_t sb  = smem_to_u32(smem);
    int*   hc  = (int*)(smem + SM_HC);
    float* sc  = (float*)(smem + SM_SC);
    unsigned long long* red = (unsigned long long*)(smem + SM_RED);

    const int tid  = threadIdx.x;
    const int lane = tid & 31;
    const int wid  = tid >> 5;
    const int warp_m = wid & 3;
    const int warp_n = wid >> 2;

    // ---- triangular tile decode: bid -> (ti, tj), tj >= ti ----
    const int bid = blockIdx.x;
    int ti = (int)(64.5f - sqrtf(64.5f * 64.5f - 2.0f * (float)bid));
    while (ti > 0  && (ti * 64 - ti * (ti - 1) / 2) > bid) --ti;
    while (((ti + 1) * 64 - (ti + 1) * ti / 2) <= bid) ++ti;
    const int tj = ti + (bid - (ti * 64 - ti * (ti - 1) / 2));
    const int row_base = ti * BM;
    const int col_base = tj * BM;

    if (tid < 128) {
        hc[tid] = host[col_base + tid];
        sc[tid] = g_sq[col_base + tid];
    }

    auto load_chunk = [&](int kc, int st) {
        const uint32_t stg = sb + SM_STG + st * STG_SZ;
#pragma unroll
        for (int hl = 0; hl < 2; ++hl) {
            const uint32_t* sbase = hl ? g_lo : g_hi;
#pragma unroll
            for (int it = 0; it < 2; ++it) {
                int idx = it * 256 + tid;
                int r = idx >> 2, c = idx & 3;
                uint32_t sw = swz(r, c);
                const uint32_t* srcA = sbase + (size_t)(row_base + r) * (D / 2) + kc * 16 + c * 4;
                const uint32_t* srcB = sbase + (size_t)(col_base + r) * (D / 2) + kc * 16 + c * 4;
                CP_ASYNC16(stg + hl * 8192 + sw, srcA);
                CP_ASYNC16(stg + 16384 + hl * 8192 + sw, srcB);
            }
        }
    };

    load_chunk(0, 0);
    CP_COMMIT();

    float acc[2][8][4];
#pragma unroll
    for (int mt = 0; mt < 2; ++mt)
#pragma unroll
        for (int nt = 0; nt < 8; ++nt)
#pragma unroll
            for (int e = 0; e < 4; ++e) acc[mt][nt][e] = 0.f;

    const int a_roff = warp_m * 32 + (lane & 7) + ((lane >> 3) & 1) * 8;
    const int a_koff = (lane >> 4);
    const int b_roff = warp_n * 64 + (lane & 7) + (lane >> 4) * 8;
    const int b_koff = ((lane >> 3) & 1);

    for (int kc = 0; kc < 8; ++kc) {
        if (kc < 7) {
            load_chunk(kc + 1, (kc + 1) & 1);
            CP_COMMIT();
            CP_WAIT1();
        } else {
            CP_WAIT0();
        }
        __syncthreads();

        const uint32_t stg = sb + SM_STG + (kc & 1) * STG_SZ;
        const uint32_t aHi = stg, aLo = stg + 8192;
        const uint32_t bHi = stg + 16384, bLo = stg + 24576;

#pragma unroll
        for (int ks = 0; ks < 2; ++ks) {
            uint32_t ah[2][4], al[2][4];
#pragma unroll
            for (int mt = 0; mt < 2; ++mt) {
                uint32_t off = swz(a_roff + mt * 16, 2 * ks + a_koff);
                LDSM_X4(ah[mt], aHi + off);
                LDSM_X4(al[mt], aLo + off);
            }
            uint32_t b0[16], b1[16];
#pragma unroll
            for (int p = 0; p < 4; ++p)
                LDSM_X4(&b0[p * 4], bHi + swz(b_roff + p * 16, 2 * ks + b_koff));
            // pass 1: hi*hi
#pragma unroll
            for (int mt = 0; mt < 2; ++mt)
#pragma unroll
                for (int nt = 0; nt < 8; ++nt) {
                    const int bi = (nt >> 1) * 4 + (nt & 1) * 2;
                    MMA16816(acc[mt][nt], ah[mt], b0[bi], b0[bi + 1]);
                }
#pragma unroll
            for (int p = 0; p < 4; ++p)
                LDSM_X4(&b1[p * 4], bLo + swz(b_roff + p * 16, 2 * ks + b_koff));
            // pass 2: lo*hi
#pragma unroll
            for (int mt = 0; mt < 2; ++mt)
#pragma unroll
                for (int nt = 0; nt < 8; ++nt) {
                    const int bi = (nt >> 1) * 4 + (nt & 1) * 2;
                    MMA16816(acc[mt][nt], al[mt], b0[bi], b0[bi + 1]);
                }
            // pass 3: hi*lo
#pragma unroll
            for (int mt = 0; mt < 2; ++mt)
#pragma unroll
                for (int nt = 0; nt < 8; ++nt) {
                    const int bi = (nt >> 1) * 4 + (nt & 1) * 2;
                    MMA16816(acc[mt][nt], ah[mt], b1[bi], b1[bi + 1]);
                }
        }
        __syncthreads();
    }

    // ======================= epilogue: both directions =======================
    int   hr[2][2];
    float sr[2][2];
#pragma unroll
    for (int mt = 0; mt < 2; ++mt)
#pragma unroll
        for (int h = 0; h < 2; ++h) {
            int r = row_base + warp_m * 32 + mt * 16 + h * 8 + (lane >> 2);
            hr[mt][h] = host[r];
            sr[mt][h] = g_sq[r];
        }

    // --- row direction ---
#pragma unroll
    for (int mt = 0; mt < 2; ++mt)
#pragma unroll
        for (int h = 0; h < 2; ++h) {
            unsigned long long key = 0xFFFFFFFFFFFFFFFFull;
            const int   hrow = hr[mt][h];
            const float srow = sr[mt][h];
#pragma unroll
            for (int nt = 0; nt < 8; ++nt)
#pragma unroll
                for (int e = 0; e < 2; ++e) {
                    const int cl = warp_n * 64 + nt * 8 + (lane & 3) * 2 + e;
                    float d2 = fmaxf(fmaf(-2.0f, acc[mt][nt][h * 2 + e], srow + sc[cl]), 0.0f);
                    if (hc[cl] != hrow) {
                        unsigned long long k =
                            ((unsigned long long)__float_as_uint(d2) << 32) |
                            (unsigned int)(col_base + cl);
                        key = umin64(key, k);
                    }
                }
            key = umin64(key, shfl_xor_u64(key, 1));
            key = umin64(key, shfl_xor_u64(key, 2));
            if ((lane & 3) == 0) {
                int rl = warp_m * 32 + mt * 16 + h * 8 + (lane >> 2);
                red[rl * 2 + warp_n] = key;
            }
        }
    __syncthreads();
    if (tid < 128) {
        unsigned long long k = umin64(red[tid * 2], red[tid * 2 + 1]);
        if (k != 0xFFFFFFFFFFFFFFFFull) atomicMin(&g_key[row_base + tid], k);
    }

    // --- col direction (skip on diagonal tiles: exact duplicate of row dir) ---
    if (ti != tj) {
#pragma unroll
        for (int nt = 0; nt < 8; ++nt)
#pragma unroll
            for (int e = 0; e < 2; ++e) {
                const int cl = warp_n * 64 + nt * 8 + (lane & 3) * 2 + e;
                const int   hcol = hc[cl];
                const float scol = sc[cl];
                unsigned long long key = 0xFFFFFFFFFFFFFFFFull;
#pragma unroll
                for (int mt = 0; mt < 2; ++mt)
#pragma unroll
                    for (int h = 0; h < 2; ++h) {
                        float d2 = fmaxf(fmaf(-2.0f, acc[mt][nt][h * 2 + e], sr[mt][h] + scol), 0.0f);
                        if (hr[mt][h] != hcol) {
                            int r = row_base + warp_m * 32 + mt * 16 + h * 8 + (lane >> 2);
                            unsigned long long k =
                                ((unsigned long long)__float_as_uint(d2) << 32) | (unsigned int)r;
                            key = umin64(key, k);
                        }
                    }
                key = umin64(key, shfl_xor_u64(key, 4));
                key = umin64(key, shfl_xor_u64(key, 8));
                key = umin64(key, shfl_xor_u64(key, 16));
                if ((lane >> 2) == 0 && key != 0xFFFFFFFFFFFFFFFFull)
                    atomicMin(&g_key[col_base + cl], key);
            }
    }
}

// ============================================================================
// Finalize: gather e_actv[idx]; 4 rows per 256-thread block.
// ============================================================================
__global__ void finalize_kernel(const float* __restrict__ A, float* __restrict__ out_an) {
    const int row = blockIdx.x * 4 + (threadIdx.x >> 6);
    const int t   = threadIdx.x & 63;
    const int idx = (int)(__ldg(&g_key[row]) & 0xFFFFFFFFu);
    const float4* src = (const float4*)(A + (size_t)idx * D);
    float4* dst = (float4*)(out_an + (size_t)row * D);
    dst[t] = src[t];
}

// No-op pad kernel: aligns ncu's "-s 5 -c 1" capture onto argmin_mma_kernel
// (4 kernels per call -> 6th workload = main kernel of call 2).
__global__ void nop_kernel() {}

// ============================================================================
extern "C" void kernel_launch(void* const* d_in, const int* in_sizes, int n_in,
                              void* d_out, int out_size) {
    const float* e_actv = (const float*)d_in[0];
    const float* e_ap   = (const float*)d_in[1];
    const int*   host   = (const int*)d_in[2];
    float* out = (float*)d_out;
    const size_t nd = (size_t)N * D;

    cudaFuncSetAttribute(argmin_mma_kernel, cudaFuncAttributeMaxDynamicSharedMemorySize, SM_TOTAL);

    prep_kernel<<<N / 8, 256>>>(e_actv, e_ap, out);
    argmin_mma_kernel<<<NBLOCKS, 256, SM_TOTAL>>>(host);
    finalize_kernel<<<N / 4, 256>>>(e_actv, out + 2 * nd);
    nop_kernel<<<1, 1>>>();
}

// round 8
// speedup vs baseline: 6.2778x; 1.0556x over previous
#include <cuda_runtime.h>
#include <cuda_bf16.h>
#include <cstdint>

#define N 8192
#define D 256
#define BM 128
#define BN 128
#define NTILES 64
#define NBLOCKS (NTILES * (NTILES + 1) / 2)   // 2080 upper-triangular tiles

// ---- smem layout (bytes): 3 stages x (Ahi,Alo,Bhi,Blo) x 8KB ----
#define SM_STG   0
#define STG_SZ   32768
#define SM_HC    (3 * STG_SZ)
#define SM_SC    (SM_HC + 512)
#define SM_RED   (SM_SC + 512)
#define SM_TOTAL (SM_RED + 2048)       // 101376 bytes -> occ 2 (202.8KB < 228KB)

// ---- device scratch (no allocation) ----
__device__ float g_sq[N];
__device__ __align__(16) uint32_t g_hi[N * (D / 2)];
__device__ __align__(16) uint32_t g_lo[N * (D / 2)];
__device__ unsigned long long g_key[N];

// ============================ PTX helpers ============================
__device__ __forceinline__ uint32_t smem_to_u32(const void* p) {
    uint32_t a;
    asm("{ .reg .u64 t; cvta.to.shared.u64 t, %1; cvt.u32.u64 %0, t; }" : "=r"(a) : "l"(p));
    return a;
}
#define CP_ASYNC16(dst, src) \
    asm volatile("cp.async.cg.shared.global [%0], [%1], 16;" :: "r"(dst), "l"(src))
#define CP_COMMIT() asm volatile("cp.async.commit_group;" ::: "memory")
#define CP_WAIT0()  asm volatile("cp.async.wait_group 0;" ::: "memory")
#define CP_WAIT1()  asm volatile("cp.async.wait_group 1;" ::: "memory")

#define LDSM_X4(r, addr) \
    asm volatile("ldmatrix.sync.aligned.m8n8.x4.shared.b16 {%0,%1,%2,%3}, [%4];" \
        : "=r"((r)[0]), "=r"((r)[1]), "=r"((r)[2]), "=r"((r)[3]) : "r"(addr))

#define MMA16816(c, a, b0, b1) \
    asm("mma.sync.aligned.m16n8k16.row.col.f32.bf16.bf16.f32 " \
        "{%0,%1,%2,%3}, {%4,%5,%6,%7}, {%8,%9}, {%0,%1,%2,%3};" \
        : "+f"((c)[0]), "+f"((c)[1]), "+f"((c)[2]), "+f"((c)[3]) \
        : "r"((a)[0]), "r"((a)[1]), "r"((a)[2]), "r"((a)[3]), "r"(b0), "r"(b1))

__device__ __forceinline__ uint32_t swz(int r, int c16) {
    return (uint32_t)(r * 64 + ((c16 ^ ((r >> 1) & 3)) << 4));
}
__device__ __forceinline__ unsigned long long shfl_xor_u64(unsigned long long v, int m) {
    uint32_t lo = (uint32_t)v, hi = (uint32_t)(v >> 32);
    lo = __shfl_xor_sync(0xffffffffu, lo, m);
    hi = __shfl_xor_sync(0xffffffffu, hi, m);
    return ((unsigned long long)hi << 32) | lo;
}
__device__ __forceinline__ unsigned long long umin64(unsigned long long a, unsigned long long b) {
    return a < b ? a : b;
}

// ============================================================================
// Fused prep: copy e_actv & e_ap to output, split A -> bf16 hi/lo, row norms,
// init keys. 8 rows per 256-thread block (one warp per row for A work).
// ============================================================================
__global__ void prep_kernel(const float* __restrict__ A, const float* __restrict__ P,
                            float* __restrict__ out) {
    const size_t nd = (size_t)N * D;
    int gid = blockIdx.x * 256 + threadIdx.x;
    if (gid < N) g_key[gid] = 0xFFFFFFFFFFFFFFFFull;

    {
        const float4* src = (const float4*)(P + (size_t)blockIdx.x * 8 * D);
        float4*       dst = (float4*)(out + nd + (size_t)blockIdx.x * 8 * D);
        dst[threadIdx.x]       = src[threadIdx.x];
        dst[threadIdx.x + 256] = src[threadIdx.x + 256];
    }

    int row  = blockIdx.x * 8 + (threadIdx.x >> 5);
    int lane = threadIdx.x & 31;
    const float4* a  = (const float4*)(A + (size_t)row * D);
    float4*       oa = (float4*)(out + (size_t)row * D);
    float s = 0.f;
#pragma unroll
    for (int q = 0; q < 2; ++q) {
        float4 v = a[lane + 32 * q];
        oa[lane + 32 * q] = v;
        s += v.x * v.x + v.y * v.y + v.z * v.z + v.w * v.w;
        __nv_bfloat162 h0 = __floats2bfloat162_rn(v.x, v.y);
        __nv_bfloat162 h1 = __floats2bfloat162_rn(v.z, v.w);
        float lx = v.x - __bfloat162float(h0.x);
        float ly = v.y - __bfloat162float(h0.y);
        float lz = v.z - __bfloat162float(h1.x);
        float lw = v.w - __bfloat162float(h1.y);
        __nv_bfloat162 l0 = __floats2bfloat162_rn(lx, ly);
        __nv_bfloat162 l1 = __floats2bfloat162_rn(lz, lw);
        uint2 hv = make_uint2(*reinterpret_cast<uint32_t*>(&h0), *reinterpret_cast<uint32_t*>(&h1));
        uint2 lv = make_uint2(*reinterpret_cast<uint32_t*>(&l0), *reinterpret_cast<uint32_t*>(&l1));
        size_t w = (size_t)row * (D / 2) + (lane + 32 * q) * 2;
        *(uint2*)(g_hi + w) = hv;
        *(uint2*)(g_lo + w) = lv;
    }
#pragma unroll
    for (int o = 16; o; o >>= 1) s += __shfl_xor_sync(0xffffffffu, s, o);
    if (lane == 0) g_sq[row] = s;
}

// ============================================================================
// Symmetric bf16x3 Gram tiles (upper-triangular) + dual-direction argmin.
// 3-stage cp.async pipeline, ONE __syncthreads per k-chunk. occ=2.
// ============================================================================
__global__ __launch_bounds__(256, 2) void argmin_mma_kernel(const int* __restrict__ host) {
    extern __shared__ char smem[];
    const uint32_t sb  = smem_to_u32(smem);
    int*   hc  = (int*)(smem + SM_HC);
    float* sc  = (float*)(smem + SM_SC);
    unsigned long long* red = (unsigned long long*)(smem + SM_RED);

    const int tid  = threadIdx.x;
    const int lane = tid & 31;
    const int wid  = tid >> 5;
    const int warp_m = wid & 3;
    const int warp_n = wid >> 2;

    // ---- triangular tile decode: bid -> (ti, tj), tj >= ti ----
    const int bid = blockIdx.x;
    int ti = (int)(64.5f - sqrtf(64.5f * 64.5f - 2.0f * (float)bid));
    while (ti > 0  && (ti * 64 - ti * (ti - 1) / 2) > bid) --ti;
    while (((ti + 1) * 64 - (ti + 1) * ti / 2) <= bid) ++ti;
    const int tj = ti + (bid - (ti * 64 - ti * (ti - 1) / 2));
    const int row_base = ti * BM;
    const int col_base = tj * BM;

    if (tid < 128) {
        hc[tid] = host[col_base + tid];
        sc[tid] = g_sq[col_base + tid];
    }

    auto load_chunk = [&](int kc, int st) {
        const uint32_t stg = sb + SM_STG + st * STG_SZ;
#pragma unroll
        for (int hl = 0; hl < 2; ++hl) {
            const uint32_t* sbase = hl ? g_lo : g_hi;
#pragma unroll
            for (int it = 0; it < 2; ++it) {
                int idx = it * 256 + tid;
                int r = idx >> 2, c = idx & 3;
                uint32_t sw = swz(r, c);
                const uint32_t* srcA = sbase + (size_t)(row_base + r) * (D / 2) + kc * 16 + c * 4;
                const uint32_t* srcB = sbase + (size_t)(col_base + r) * (D / 2) + kc * 16 + c * 4;
                CP_ASYNC16(stg + hl * 8192 + sw, srcA);
                CP_ASYNC16(stg + 16384 + hl * 8192 + sw, srcB);
            }
        }
    };

    // prologue: 2 chunks in flight
    load_chunk(0, 0); CP_COMMIT();
    load_chunk(1, 1); CP_COMMIT();

    float acc[2][8][4];
#pragma unroll
    for (int mt = 0; mt < 2; ++mt)
#pragma unroll
        for (int nt = 0; nt < 8; ++nt)
#pragma unroll
            for (int e = 0; e < 4; ++e) acc[mt][nt][e] = 0.f;

    const int a_roff = warp_m * 32 + (lane & 7) + ((lane >> 3) & 1) * 8;
    const int a_koff = (lane >> 4);
    const int b_roff = warp_n * 64 + (lane & 7) + (lane >> 4) * 8;
    const int b_koff = ((lane >> 3) & 1);

    for (int kc = 0; kc < 8; ++kc) {
        if (kc < 7) CP_WAIT1(); else CP_WAIT0();
        __syncthreads();   // publishes chunk kc; also guards stage reuse below

        // prefetch chunk kc+2 into stage (kc+2)%3 (the stage compute(kc-1) read)
        if (kc + 2 < 8) {
            load_chunk(kc + 2, (kc + 2) % 3);
            CP_COMMIT();
        }

        const uint32_t stg = sb + SM_STG + (kc % 3) * STG_SZ;
        const uint32_t aHi = stg, aLo = stg + 8192;
        const uint32_t bHi = stg + 16384, bLo = stg + 24576;

#pragma unroll
        for (int ks = 0; ks < 2; ++ks) {
            uint32_t ah[2][4], al[2][4];
#pragma unroll
            for (int mt = 0; mt < 2; ++mt) {
                uint32_t off = swz(a_roff + mt * 16, 2 * ks + a_koff);
                LDSM_X4(ah[mt], aHi + off);
                LDSM_X4(al[mt], aLo + off);
            }
            uint32_t b0[16], b1[16];
#pragma unroll
            for (int p = 0; p < 4; ++p)
                LDSM_X4(&b0[p * 4], bHi + swz(b_roff + p * 16, 2 * ks + b_koff));
            // pass 1: hi*hi
#pragma unroll
            for (int mt = 0; mt < 2; ++mt)
#pragma unroll
                for (int nt = 0; nt < 8; ++nt) {
                    const int bi = (nt >> 1) * 4 + (nt & 1) * 2;
                    MMA16816(acc[mt][nt], ah[mt], b0[bi], b0[bi + 1]);
                }
#pragma unroll
            for (int p = 0; p < 4; ++p)
                LDSM_X4(&b1[p * 4], bLo + swz(b_roff + p * 16, 2 * ks + b_koff));
            // pass 2: lo*hi
#pragma unroll
            for (int mt = 0; mt < 2; ++mt)
#pragma unroll
                for (int nt = 0; nt < 8; ++nt) {
                    const int bi = (nt >> 1) * 4 + (nt & 1) * 2;
                    MMA16816(acc[mt][nt], al[mt], b0[bi], b0[bi + 1]);
                }
            // pass 3: hi*lo
#pragma unroll
            for (int mt = 0; mt < 2; ++mt)
#pragma unroll
                for (int nt = 0; nt < 8; ++nt) {
                    const int bi = (nt >> 1) * 4 + (nt & 1) * 2;
                    MMA16816(acc[mt][nt], ah[mt], b1[bi], b1[bi + 1]);
                }
        }
    }
    __syncthreads();   // all compute done before epilogue reuses red[]

    // ======================= epilogue: both directions =======================
    int   hr[2][2];
    float sr[2][2];
#pragma unroll
    for (int mt = 0; mt < 2; ++mt)
#pragma unroll
        for (int h = 0; h < 2; ++h) {
            int r = row_base + warp_m * 32 + mt * 16 + h * 8 + (lane >> 2);
            hr[mt][h] = host[r];
            sr[mt][h] = g_sq[r];
        }

    // --- row direction ---
#pragma unroll
    for (int mt = 0; mt < 2; ++mt)
#pragma unroll
        for (int h = 0; h < 2; ++h) {
            unsigned long long key = 0xFFFFFFFFFFFFFFFFull;
            const int   hrow = hr[mt][h];
            const float srow = sr[mt][h];
#pragma unroll
            for (int nt = 0; nt < 8; ++nt)
#pragma unroll
                for (int e = 0; e < 2; ++e) {
                    const int cl = warp_n * 64 + nt * 8 + (lane & 3) * 2 + e;
                    float d2 = fmaxf(fmaf(-2.0f, acc[mt][nt][h * 2 + e], srow + sc[cl]), 0.0f);
                    if (hc[cl] != hrow) {
                        unsigned long long k =
                            ((unsigned long long)__float_as_uint(d2) << 32) |
                            (unsigned int)(col_base + cl);
                        key = umin64(key, k);
                    }
                }
            key = umin64(key, shfl_xor_u64(key, 1));
            key = umin64(key, shfl_xor_u64(key, 2));
            if ((lane & 3) == 0) {
                int rl = warp_m * 32 + mt * 16 + h * 8 + (lane >> 2);
                red[rl * 2 + warp_n] = key;
            }
        }
    __syncthreads();
    if (tid < 128) {
        unsigned long long k = umin64(red[tid * 2], red[tid * 2 + 1]);
        if (k != 0xFFFFFFFFFFFFFFFFull) atomicMin(&g_key[row_base + tid], k);
    }

    // --- col direction (skip on diagonal tiles: exact duplicate of row dir) ---
    if (ti != tj) {
#pragma unroll
        for (int nt = 0; nt < 8; ++nt)
#pragma unroll
            for (int e = 0; e < 2; ++e) {
                const int cl = warp_n * 64 + nt * 8 + (lane & 3) * 2 + e;
                const int   hcol = hc[cl];
                const float scol = sc[cl];
                unsigned long long key = 0xFFFFFFFFFFFFFFFFull;
#pragma unroll
                for (int mt = 0; mt < 2; ++mt)
#pragma unroll
                    for (int h = 0; h < 2; ++h) {
                        float d2 = fmaxf(fmaf(-2.0f, acc[mt][nt][h * 2 + e], sr[mt][h] + scol), 0.0f);
                        if (hr[mt][h] != hcol) {
                            int r = row_base + warp_m * 32 + mt * 16 + h * 8 + (lane >> 2);
                            unsigned long long k =
                                ((unsigned long long)__float_as_uint(d2) << 32) | (unsigned int)r;
                            key = umin64(key, k);
                        }
                    }
                key = umin64(key, shfl_xor_u64(key, 4));
                key = umin64(key, shfl_xor_u64(key, 8));
                key = umin64(key, shfl_xor_u64(key, 16));
                if ((lane >> 2) == 0 && key != 0xFFFFFFFFFFFFFFFFull)
                    atomicMin(&g_key[col_base + cl], key);
            }
    }
}

// ============================================================================
// Finalize: gather e_actv[idx]; 4 rows per 256-thread block.
// ============================================================================
__global__ void finalize_kernel(const float* __restrict__ A, float* __restrict__ out_an) {
    const int row = blockIdx.x * 4 + (threadIdx.x >> 6);
    const int t   = threadIdx.x & 63;
    const int idx = (int)(__ldg(&g_key[row]) & 0xFFFFFFFFu);
    const float4* src = (const float4*)(A + (size_t)idx * D);
    float4* dst = (float4*)(out_an + (size_t)row * D);
    dst[t] = src[t];
}

// ============================================================================
extern "C" void kernel_launch(void* const* d_in, const int* in_sizes, int n_in,
                              void* d_out, int out_size) {
    const float* e_actv = (const float*)d_in[0];
    const float* e_ap   = (const float*)d_in[1];
    const int*   host   = (const int*)d_in[2];
    float* out = (float*)d_out;
    const size_t nd = (size_t)N * D;

    cudaFuncSetAttribute(argmin_mma_kernel, cudaFuncAttributeMaxDynamicSharedMemorySize, SM_TOTAL);

    prep_kernel<<<N / 8, 256>>>(e_actv, e_ap, out);
    argmin_mma_kernel<<<NBLOCKS, 256, SM_TOTAL>>>(host);
    finalize_kernel<<<N / 4, 256>>>(e_actv, out + 2 * nd);
}